// round 9
// baseline (speedup 1.0000x reference)
#include <cuda_runtime.h>
#include <cuda_bf16.h>
#include <math.h>

#define BB    2304
#define CH    22
#define TP    250
#define ST    64
#define KW    13
#define RR    32
#define NFE   528

typedef unsigned long long ull;

__device__ float g_z[(size_t)BB * ST * TP];
__device__ float g_y[(size_t)BB * RR * RR];
__device__ float g_xp[(size_t)BB * CH * 272];   // pooled + padded input
__device__ ull   g_w2[ST * 286];                // (w,w) packed weights

__device__ __forceinline__ ull pk2(float a, float b) {
    ull r;
    asm("mov.b64 %0, {%1, %2};" : "=l"(r)
        : "r"(__float_as_uint(a)), "r"(__float_as_uint(b)));
    return r;
}
__device__ __forceinline__ void upk2(ull v, float &a, float &b) {
    unsigned int lo, hi;
    asm("mov.b64 {%0, %1}, %2;" : "=r"(lo), "=r"(hi) : "l"(v));
    a = __uint_as_float(lo); b = __uint_as_float(hi);
}
__device__ __forceinline__ void fma2(ull &d, ull a, ull b) {
    asm("fma.rn.f32x2 %0, %1, %2, %0;" : "+l"(d) : "l"(a), "l"(b));
}

// ============================================================
// K0a: pool(4) + zero-pad once per b -> g_xp[b][c][272]
// ============================================================
__global__ void __launch_bounds__(128)
k_prep(const float* __restrict__ x)
{
    int b = blockIdx.x, tid = threadIdx.x;
    const float4* xb = (const float4*)(x + (size_t)b * CH * 1000);
    float* dst = g_xp + (size_t)b * CH * 272;
    for (int i = tid; i < CH * 272; i += 128) {
        int c = i / 272, tt = i - c * 272;
        float v = 0.f;
        if (tt >= 6 && tt < 256) {
            float4 p = xb[c * TP + (tt - 6)];
            v = 0.25f * (p.x + p.y + p.z + p.w);
        }
        dst[i] = v;
    }
}

// K0b: pack conv weights as (w,w) ull pairs
__global__ void __launch_bounds__(256)
k_wpack(const float* __restrict__ cw)
{
    int i = blockIdx.x * 256 + threadIdx.x;
    if (i < ST * 286) {
        float w = cw[i];
        g_w2[i] = pk2(w, w);
    }
}

// ============================================================
// K1: conv(22x13) + BN -> g_z[b][o][t]
// ONE block per b, 512 threads, ONE unit per thread:
//   warp = t-chunk (16 chunks x 16 t), lane = o-pair (32 pairs).
// smem: xp floats (23.9KB) + w2s 64 x 287 ull (146.9KB) = ~171KB
//   -> 1 block/SM, 16 warps/SM, 4 warps/SMSP.
// Per c: 7 LDS.128 (broadcast) + 27 pk2 + 2x(13 LDS.64 + 104 FFMA2).
// ============================================================
#define W2S_PITCH 287
#define CONV_SMEM (CH * 272 * 4 + ST * W2S_PITCH * 8)

__global__ void __launch_bounds__(512, 1)
k_conv(const float* __restrict__ cb, const float* __restrict__ bg,
       const float* __restrict__ bbv, const float* __restrict__ bm,
       const float* __restrict__ bv)
{
    extern __shared__ float dsm[];
    float* xp  = dsm;                               // CH*272 floats
    ull*   w2s = (ull*)(dsm + CH * 272);            // 64 x 287 ull
    __shared__ float sc[64], sh[64];

    int b = blockIdx.x, tid = threadIdx.x;

    // setup: pooled input + packed weights + BN constants
    {
        const float4* src = (const float4*)(g_xp + (size_t)b * CH * 272);
        float4* d4 = (float4*)xp;
        for (int i = tid; i < CH * 272 / 4; i += 512) d4[i] = src[i];
        for (int i = tid; i < ST * 286; i += 512) {
            int o = i / 286, k = i - o * 286;
            w2s[o * W2S_PITCH + k] = g_w2[i];
        }
        if (tid < 64) {
            float inv = bg[tid] * rsqrtf(bv[tid] + 1e-5f);
            sc[tid] = inv;
            sh[tid] = cb[tid] * inv + bbv[tid] - bm[tid] * inv;
        }
    }
    __syncthreads();

    int chunk = tid >> 5;          // 0..15
    int opair = tid & 31;          // 0..31
    int t0 = chunk * 16;
    int o0 = opair * 2;

    ull acc[2][8];
    #pragma unroll
    for (int oh = 0; oh < 2; ++oh)
        #pragma unroll
        for (int u = 0; u < 8; ++u) acc[oh][u] = 0ull;

    #pragma unroll 1
    for (int c = 0; c < CH; ++c) {
        // window: 28 floats starting at xp[c*272 + t0] (16B aligned)
        const float4* pw = (const float4*)(xp + c * 272 + t0);
        float p[28];
        #pragma unroll
        for (int q = 0; q < 7; ++q) {
            float4 v = pw[q];
            p[4 * q] = v.x; p[4 * q + 1] = v.y;
            p[4 * q + 2] = v.z; p[4 * q + 3] = v.w;
        }
        ull xe[14], xo[13];
        #pragma unroll
        for (int j = 0; j < 14; ++j) xe[j] = pk2(p[2 * j], p[2 * j + 1]);
        #pragma unroll
        for (int j = 0; j < 13; ++j) xo[j] = pk2(p[2 * j + 1], p[2 * j + 2]);

        #pragma unroll
        for (int oh = 0; oh < 2; ++oh) {
            const ull* wr = w2s + (o0 + oh) * W2S_PITCH + c * 13;
            #pragma unroll
            for (int k = 0; k < 13; ++k) {
                ull wv = wr[k];
                int m = k >> 1;
                if ((k & 1) == 0) {
                    #pragma unroll
                    for (int u = 0; u < 8; ++u) fma2(acc[oh][u], xe[m + u], wv);
                } else {
                    #pragma unroll
                    for (int u = 0; u < 8; ++u) fma2(acc[oh][u], xo[m + u], wv);
                }
            }
        }
    }

    // epilogue: BN + store (float2, (250*o + t0) even)
    #pragma unroll
    for (int oh = 0; oh < 2; ++oh) {
        int o = o0 + oh;
        float scl = sc[o], shf = sh[o];
        float2* zr = (float2*)(g_z + ((size_t)b * ST + o) * TP + t0);
        #pragma unroll
        for (int u = 0; u < 8; ++u) {
            int t = t0 + 2 * u;
            if (t < TP) {
                float lov, hiv; upk2(acc[oh][u], lov, hiv);
                float2 st;
                st.x = lov * scl + shf;
                st.y = hiv * scl + shf;
                zr[u] = st;
            }
        }
    }
}

// ============================================================
// K2: covmap (unchanged from R8).
//   A = Sum_blk rtr*(Z Z^T - s1 s1^T / l),  y = (1/3) W A W^T + 1e-5 W W^T
// ============================================================
__global__ void __launch_bounds__(256, 2)
k_covmap(const float* __restrict__ W)
{
    __shared__ __align__(16) float zs[64 * 92];
    __shared__ __align__(16) float Wsh[32 * 64];
    __shared__ __align__(16) float Bsh[32 * 72];
    __shared__ float s1sh[64];
    __shared__ float redv[64];
    __shared__ float s_rtr;

    int b = blockIdx.x, tid = threadIdx.x;
    int ti = tid >> 4, tj = tid & 15;

    for (int i = tid; i < 2048; i += 256) Wsh[i] = W[i];

    const int offs[3] = {0, 84, 167};
    const int lens[3] = {84, 83, 83};

    float acc[4][4];
    #pragma unroll
    for (int a = 0; a < 4; ++a)
        #pragma unroll
        for (int e = 0; e < 4; ++e) acc[a][e] = 0.f;

    for (int blk = 0; blk < 3; ++blk) {
        int off = offs[blk], l = lens[blk];
        float flin = 1.f / (float)l;
        __syncthreads();
        for (int i = tid; i < 64 * 92; i += 256) {
            int c = i / 92, t = i - c * 92;
            zs[i] = (t < l) ? g_z[((size_t)b * 64 + c) * TP + off + t] : 0.f;
        }
        __syncthreads();
        {
            int c = tid >> 2, q = tid & 3;
            const float4* zr = (const float4*)(zs + c * 92);
            float s1 = 0.f, s2 = 0.f;
            for (int t4 = q; t4 < 23; t4 += 4) {
                float4 v = zr[t4];
                s1 += v.x + v.y + v.z + v.w;
                s2 += v.x * v.x + v.y * v.y + v.z * v.z + v.w * v.w;
            }
            s1 += __shfl_xor_sync(0xffffffffu, s1, 1);
            s2 += __shfl_xor_sync(0xffffffffu, s2, 1);
            s1 += __shfl_xor_sync(0xffffffffu, s1, 2);
            s2 += __shfl_xor_sync(0xffffffffu, s2, 2);
            if (q == 0) { s1sh[c] = s1; redv[c] = s2 - s1 * s1 * flin; }
        }
        __syncthreads();
        if (tid < 32) {
            float v = redv[tid] + redv[tid + 32];
            v += __shfl_xor_sync(0xffffffffu, v, 16);
            v += __shfl_xor_sync(0xffffffffu, v, 8);
            v += __shfl_xor_sync(0xffffffffu, v, 4);
            v += __shfl_xor_sync(0xffffffffu, v, 2);
            v += __shfl_xor_sync(0xffffffffu, v, 1);
            if (tid == 0) s_rtr = 1.f / v;
        }
        __syncthreads();

        ull zz2[4][4];
        #pragma unroll
        for (int a = 0; a < 4; ++a)
            #pragma unroll
            for (int e = 0; e < 4; ++e) zz2[a][e] = 0ull;

        const ulonglong2* Z2 = (const ulonglong2*)zs;
        #pragma unroll 1
        for (int t4 = 0; t4 < 23; ++t4) {
            ulonglong2 uu[4], vv[4];
            #pragma unroll
            for (int a = 0; a < 4; ++a) uu[a] = Z2[(ti + 16 * a) * 23 + t4];
            #pragma unroll
            for (int e = 0; e < 4; ++e) vv[e] = Z2[(tj + 16 * e) * 23 + t4];
            #pragma unroll
            for (int a = 0; a < 4; ++a)
                #pragma unroll
                for (int e = 0; e < 4; ++e) {
                    fma2(zz2[a][e], uu[a].x, vv[e].x);
                    fma2(zz2[a][e], uu[a].y, vv[e].y);
                }
        }
        float rtr = s_rtr;
        #pragma unroll
        for (int a = 0; a < 4; ++a) {
            float s1i = s1sh[ti + 16 * a] * flin * rtr;
            #pragma unroll
            for (int e = 0; e < 4; ++e) {
                float lo, hi; upk2(zz2[a][e], lo, hi);
                acc[a][e] += rtr * (lo + hi) - s1i * s1sh[tj + 16 * e];
            }
        }
    }
    __syncthreads();
    {
        float* A = zs;
        #pragma unroll
        for (int a = 0; a < 4; ++a)
            #pragma unroll
            for (int e = 0; e < 4; ++e)
                A[(ti + 16 * a) * 68 + tj + 16 * e] = acc[a][e];
    }
    __syncthreads();
    {
        const ulonglong2* A2 = (const ulonglong2*)zs;
        ulonglong2* B2 = (ulonglong2*)Bsh;
        #pragma unroll
        for (int pass = 0; pass < 2; ++pass) {
            int u0 = tid + pass * 256;
            int o = u0 >> 4, c4 = u0 & 15;
            ull a2a = 0ull, a2b = 0ull;
            const float* wrow = Wsh + o * 64;
            #pragma unroll 4
            for (int k = 0; k < 64; ++k) {
                float w = wrow[k];
                ull w2 = pk2(w, w);
                ulonglong2 av = A2[k * 17 + c4];
                fma2(a2a, av.x, w2);
                fma2(a2b, av.y, w2);
            }
            ulonglong2 st; st.x = a2a; st.y = a2b;
            B2[o * 18 + c4] = st;
        }
    }
    __syncthreads();
    if (tid < 64) {
        int o0 = (tid >> 3) * 4, p0 = (tid & 7) * 4;
        ull y2[4][4], wa2[4][4];
        #pragma unroll
        for (int a = 0; a < 4; ++a)
            #pragma unroll
            for (int e = 0; e < 4; ++e) { y2[a][e] = 0ull; wa2[a][e] = 0ull; }

        const ulonglong2* B2 = (const ulonglong2*)Bsh;
        const ulonglong2* W2 = (const ulonglong2*)Wsh;
        #pragma unroll 2
        for (int c4 = 0; c4 < 16; ++c4) {
            ulonglong2 bo[4], wo[4], wp[4];
            #pragma unroll
            for (int a = 0; a < 4; ++a) {
                bo[a] = B2[(o0 + a) * 18 + c4];
                wo[a] = W2[(o0 + a) * 16 + c4];
            }
            #pragma unroll
            for (int e = 0; e < 4; ++e) wp[e] = W2[(p0 + e) * 16 + c4];
            #pragma unroll
            for (int a = 0; a < 4; ++a)
                #pragma unroll
                for (int e = 0; e < 4; ++e) {
                    fma2(y2[a][e], bo[a].x, wp[e].x);
                    fma2(y2[a][e], bo[a].y, wp[e].y);
                    fma2(wa2[a][e], wo[a].x, wp[e].x);
                    fma2(wa2[a][e], wo[a].y, wp[e].y);
                }
        }
        #pragma unroll
        for (int a = 0; a < 4; ++a) {
            float4 ov;
            float lo, hi, wl, wh;
            upk2(y2[a][0], lo, hi); upk2(wa2[a][0], wl, wh);
            ov.x = (lo + hi) * (1.f / 3.f) + 1e-5f * (wl + wh);
            upk2(y2[a][1], lo, hi); upk2(wa2[a][1], wl, wh);
            ov.y = (lo + hi) * (1.f / 3.f) + 1e-5f * (wl + wh);
            upk2(y2[a][2], lo, hi); upk2(wa2[a][2], wl, wh);
            ov.z = (lo + hi) * (1.f / 3.f) + 1e-5f * (wl + wh);
            upk2(y2[a][3], lo, hi); upk2(wa2[a][3], wl, wh);
            ov.w = (lo + hi) * (1.f / 3.f) + 1e-5f * (wl + wh);
            *(float4*)(g_y + (size_t)b * 1024 + (o0 + a) * 32 + p0) = ov;
        }
    }
}

// ============================================================
// K3: one warp per 32x32 SPD: Hestenes Jacobi (6 sweeps),
//     logm = U log(max(lam,1e-4)) U^T, scaled triu -> fe
// ============================================================
__global__ void __launch_bounds__(256)
k_eig(float* __restrict__ feout)
{
    __shared__ float sm[8 * 1088];

    int tid = threadIdx.x;
    int wid = tid >> 5, lane = tid & 31;
    int b = blockIdx.x * 8 + wid;
    if (b >= BB) return;

    const float* Y = g_y + (size_t)b * 1024;
    float a[32];
    #pragma unroll
    for (int i = 0; i < 32; ++i) a[i] = Y[i * 32 + lane];

    for (int sweep = 0; sweep < 6; ++sweep) {
        for (int r = 0; r < 31; ++r) {
            int partner;
            if (lane == 0) partner = (30 + r) % 31 + 1;
            else {
                int pos = ((lane - 1 - r) % 31 + 31) % 31 + 1;
                int pp = 31 - pos;
                partner = (pp == 0) ? 0 : ((pp - 1 + r) % 31) + 1;
            }
            float oth[32];
            #pragma unroll
            for (int i = 0; i < 32; ++i)
                oth[i] = __shfl_sync(0xffffffffu, a[i], partner);
            float own = 0.f, dot = 0.f;
            #pragma unroll
            for (int i = 0; i < 32; ++i) { own += a[i] * a[i]; dot += a[i] * oth[i]; }
            float othn = __shfl_sync(0xffffffffu, own, partner);
            bool isp = lane < partner;
            float app = isp ? own : othn;
            float aqq = isp ? othn : own;
            float c = 1.f, s = 0.f;
            if (dot * dot > 1e-24f * app * aqq) {
                float zeta = (aqq - app) / (2.f * dot);
                float t = ((zeta >= 0.f) ? 1.f : -1.f) /
                          (fabsf(zeta) + sqrtf(1.f + zeta * zeta));
                c = rsqrtf(1.f + t * t);
                s = c * t;
            }
            #pragma unroll
            for (int i = 0; i < 32; ++i)
                a[i] = isp ? (c * a[i] - s * oth[i]) : (s * oth[i] + c * a[i]);
        }
    }

    float own = 0.f;
    #pragma unroll
    for (int i = 0; i < 32; ++i) own += a[i] * a[i];
    float lam = sqrtf(own);
    float g = logf(fmaxf(lam, 1e-4f));
    float inv = 1.f / lam;

    float* Us = sm + wid * 1088;
    float* gs = Us + 1056;
    #pragma unroll
    for (int i = 0; i < 32; ++i) Us[lane * 33 + i] = a[i] * inv;
    gs[lane] = g;
    __syncwarp();

    float scal[32];
    #pragma unroll
    for (int j = 0; j < 32; ++j) scal[j] = gs[j] * Us[j * 33 + lane];
    float acc[32];
    #pragma unroll
    for (int i = 0; i < 32; ++i) acc[i] = 0.f;
    #pragma unroll
    for (int j = 0; j < 32; ++j) {
        float sj = scal[j];
        #pragma unroll
        for (int i = 0; i < 32; ++i) acc[i] += sj * Us[j * 33 + i];
    }

    const float SQ2 = 1.41421356237309515f;
    int bi = 32 * lane - (lane * (lane - 1)) / 2 - lane;
    float* fb = feout + (size_t)b * NFE + bi;
    #pragma unroll
    for (int j = 0; j < 32; ++j) {
        if (j >= lane) fb[j] = acc[j] * ((j == lane) ? 1.f : SQ2);
    }
}

// ============================================================
// K4: logits(256,4) = fe(256,4752) @ Wl(4,4752)^T + bl
// ============================================================
__global__ void __launch_bounds__(128)
k_linear(const float* __restrict__ fe, const float* __restrict__ Wl,
         const float* __restrict__ bl, float* __restrict__ out)
{
    __shared__ float red[128 * 4];
    int bs = blockIdx.x, tid = threadIdx.x;
    const float* fr = fe + (size_t)bs * 4752;
    float acc[4] = {0.f, 0.f, 0.f, 0.f};
    for (int i = tid; i < 4752; i += 128) {
        float v = fr[i];
        #pragma unroll
        for (int c = 0; c < 4; ++c) acc[c] += v * Wl[c * 4752 + i];
    }
    #pragma unroll
    for (int c = 0; c < 4; ++c) red[tid * 4 + c] = acc[c];
    __syncthreads();
    for (int s = 64; s > 0; s >>= 1) {
        if (tid < s) {
            #pragma unroll
            for (int c = 0; c < 4; ++c) red[tid * 4 + c] += red[(tid + s) * 4 + c];
        }
        __syncthreads();
    }
    if (tid < 4) out[bs * 4 + tid] = red[tid] + bl[tid];
}

extern "C" void kernel_launch(void* const* d_in, const int* in_sizes, int n_in,
                              void* d_out, int out_size) {
    const float* x   = (const float*)d_in[0];
    const float* cw  = (const float*)d_in[1];
    const float* cb  = (const float*)d_in[2];
    const float* bg  = (const float*)d_in[3];
    const float* bb  = (const float*)d_in[4];
    const float* bm  = (const float*)d_in[5];
    const float* bv  = (const float*)d_in[6];
    const float* W   = (const float*)d_in[7];
    const float* Wl  = (const float*)d_in[8];
    const float* bl  = (const float*)d_in[9];
    float* fe     = (float*)d_out;
    float* logits = fe + (size_t)BB * NFE;

    static int smem_set = 0;
    if (!smem_set) {
        cudaFuncSetAttribute(k_conv, cudaFuncAttributeMaxDynamicSharedMemorySize,
                             CONV_SMEM);
        smem_set = 1;
    }

    k_wpack<<<(ST * 286 + 255) / 256, 256>>>(cw);
    k_prep<<<BB, 128>>>(x);
    k_conv<<<BB, 512, CONV_SMEM>>>(cb, bg, bb, bm, bv);
    k_covmap<<<BB, 256>>>(W);
    k_eig<<<BB / 8, 256>>>(fe);
    k_linear<<<256, 128>>>(fe, Wl, bl, logits);
}

// round 12
// speedup vs baseline: 1.1475x; 1.1475x over previous
#include <cuda_runtime.h>
#include <cuda_bf16.h>
#include <math.h>

#define BB    2304
#define CH    22
#define TP    250
#define ST    64
#define KW    13
#define RR    32
#define NFE   528

typedef unsigned long long ull;

__device__ float g_z[(size_t)BB * ST * TP];
__device__ float g_y[(size_t)BB * RR * RR];
__device__ float g_xp[(size_t)BB * CH * 272];   // pooled + padded input
__device__ ull   g_w2[ST * 286];                // (w,w) packed weights

__device__ __forceinline__ ull pk2(float a, float b) {
    ull r;
    asm("mov.b64 %0, {%1, %2};" : "=l"(r)
        : "r"(__float_as_uint(a)), "r"(__float_as_uint(b)));
    return r;
}
__device__ __forceinline__ void upk2(ull v, float &a, float &b) {
    unsigned int lo, hi;
    asm("mov.b64 {%0, %1}, %2;" : "=r"(lo), "=r"(hi) : "l"(v));
    a = __uint_as_float(lo); b = __uint_as_float(hi);
}
__device__ __forceinline__ void fma2(ull &d, ull a, ull b) {
    asm("fma.rn.f32x2 %0, %1, %2, %0;" : "+l"(d) : "l"(a), "l"(b));
}

// ============================================================
// K0a: pool(4) + zero-pad once per b -> g_xp[b][c][272]
// ============================================================
__global__ void __launch_bounds__(128)
k_prep(const float* __restrict__ x)
{
    int b = blockIdx.x, tid = threadIdx.x;
    const float4* xb = (const float4*)(x + (size_t)b * CH * 1000);
    float* dst = g_xp + (size_t)b * CH * 272;
    for (int i = tid; i < CH * 272; i += 128) {
        int c = i / 272, tt = i - c * 272;
        float v = 0.f;
        if (tt >= 6 && tt < 256) {
            float4 p = xb[c * TP + (tt - 6)];
            v = 0.25f * (p.x + p.y + p.z + p.w);
        }
        dst[i] = v;
    }
}

// K0b: pack conv weights as (w,w) ull pairs
__global__ void __launch_bounds__(256)
k_wpack(const float* __restrict__ cw)
{
    int i = blockIdx.x * 256 + threadIdx.x;
    if (i < ST * 286) {
        float w = cw[i];
        g_w2[i] = pk2(w, w);
    }
}

// ============================================================
// K1: conv(22x13) + BN -> g_z[b][o][t]
// grid (2, BB): og = 32 o's. 256 threads, 2 blocks/SM (~97.5KB).
// thread -> chunk = tid&15 (16 t at t0=16*chunk), o's {ol, ol+16},
//   ol = tid>>4. Window shared across both o's.
// Dual-phase accumulators: even-k taps -> A_u = (y[2u], y[2u+1]);
// odd-k taps -> B_u = (y[2u-1], y[2u]); BOTH use only aligned
// f32x2 pairs e[j] from 7 LDS.128 -> no packing MOVs at all.
// ============================================================
#define W2S_PITCH 287
#define CONV_SMEM (CH * 272 * 4 + 32 * W2S_PITCH * 8)

__global__ void __launch_bounds__(256, 2)
k_conv(const float* __restrict__ cb, const float* __restrict__ bg,
       const float* __restrict__ bbv, const float* __restrict__ bm,
       const float* __restrict__ bv)
{
    extern __shared__ float dsm[];
    float* xp  = dsm;                               // CH*272 floats
    ull*   w2s = (ull*)(dsm + CH * 272);            // 32 x 287 ull
    __shared__ float sc[32], sh[32];

    int og = blockIdx.x, b = blockIdx.y, tid = threadIdx.x;

    // setup
    {
        const float4* src = (const float4*)(g_xp + (size_t)b * CH * 272);
        float4* d4 = (float4*)xp;
        for (int i = tid; i < CH * 272 / 4; i += 256) d4[i] = src[i];
        const ull* wsrc = g_w2 + og * 32 * 286;
        for (int i = tid; i < 32 * 286; i += 256) {
            int ol = i / 286, k = i - ol * 286;
            w2s[ol * W2S_PITCH + k] = wsrc[i];
        }
        if (tid < 32) {
            int o = og * 32 + tid;
            float inv = bg[o] * rsqrtf(bv[o] + 1e-5f);
            sc[tid] = inv;
            sh[tid] = cb[o] * inv + bbv[o] - bm[o] * inv;
        }
    }
    __syncthreads();

    int chunk = tid & 15;
    int ol0   = tid >> 4;          // first o: ol0, second: ol0+16
    int t0 = chunk * 16;

    ull A[2][8], Bv[2][9];
    #pragma unroll
    for (int oh = 0; oh < 2; ++oh) {
        #pragma unroll
        for (int u = 0; u < 8; ++u) A[oh][u] = 0ull;
        #pragma unroll
        for (int u = 0; u < 9; ++u) Bv[oh][u] = 0ull;
    }

    #pragma unroll 1
    for (int c = 0; c < CH; ++c) {
        // aligned pair window: e[j] = (xp[base+2j], xp[base+2j+1]), j=0..13
        const ulonglong2* pw = (const ulonglong2*)(xp + c * 272 + t0);
        ull e[14];
        #pragma unroll
        for (int q = 0; q < 7; ++q) {
            ulonglong2 v = pw[q];
            e[2 * q] = v.x; e[2 * q + 1] = v.y;
        }

        #pragma unroll
        for (int oh = 0; oh < 2; ++oh) {
            const ull* wr = w2s + (ol0 + oh * 16) * W2S_PITCH + c * 13;
            // even taps k = 2m : A_u += w * e[m+u]
            #pragma unroll
            for (int m = 0; m < 7; ++m) {
                ull wv = wr[2 * m];
                #pragma unroll
                for (int u = 0; u < 8; ++u) fma2(A[oh][u], e[m + u], wv);
            }
            // odd taps k = 2m+1 : B_u += w * e[m+u]  (u = 0..8)
            #pragma unroll
            for (int m = 0; m < 6; ++m) {
                ull wv = wr[2 * m + 1];
                #pragma unroll
                for (int u = 0; u < 9; ++u) fma2(Bv[oh][u], e[m + u], wv);
            }
        }
    }

    // epilogue: stitch phases, BN, store
    #pragma unroll
    for (int oh = 0; oh < 2; ++oh) {
        int ol = ol0 + oh * 16;
        int o = og * 32 + ol;
        float scl = sc[ol], shf = sh[ol];
        float2* zr = (float2*)(g_z + ((size_t)b * ST + o) * TP + t0);
        #pragma unroll
        for (int u = 0; u < 8; ++u) {
            int t = t0 + 2 * u;
            if (t < TP) {
                float alo, ahi, blo, bhi, nlo, nhi;
                upk2(A[oh][u], alo, ahi);
                upk2(Bv[oh][u], blo, bhi);
                upk2(Bv[oh][u + 1], nlo, nhi);
                float ylo = alo + bhi;     // y[t0+2u]
                float yhi = ahi + nlo;     // y[t0+2u+1]
                float2 st;
                st.x = ylo * scl + shf;
                st.y = yhi * scl + shf;
                zr[u] = st;
            }
        }
    }
}

// ============================================================
// K2: covmap (unchanged from R8).
//   A = Sum_blk rtr*(Z Z^T - s1 s1^T / l),  y = (1/3) W A W^T + 1e-5 W W^T
// ============================================================
__global__ void __launch_bounds__(256, 2)
k_covmap(const float* __restrict__ W)
{
    __shared__ __align__(16) float zs[64 * 92];
    __shared__ __align__(16) float Wsh[32 * 64];
    __shared__ __align__(16) float Bsh[32 * 72];
    __shared__ float s1sh[64];
    __shared__ float redv[64];
    __shared__ float s_rtr;

    int b = blockIdx.x, tid = threadIdx.x;
    int ti = tid >> 4, tj = tid & 15;

    for (int i = tid; i < 2048; i += 256) Wsh[i] = W[i];

    const int offs[3] = {0, 84, 167};
    const int lens[3] = {84, 83, 83};

    float acc[4][4];
    #pragma unroll
    for (int a = 0; a < 4; ++a)
        #pragma unroll
        for (int e = 0; e < 4; ++e) acc[a][e] = 0.f;

    for (int blk = 0; blk < 3; ++blk) {
        int off = offs[blk], l = lens[blk];
        float flin = 1.f / (float)l;
        __syncthreads();
        for (int i = tid; i < 64 * 92; i += 256) {
            int c = i / 92, t = i - c * 92;
            zs[i] = (t < l) ? g_z[((size_t)b * 64 + c) * TP + off + t] : 0.f;
        }
        __syncthreads();
        {
            int c = tid >> 2, q = tid & 3;
            const float4* zr = (const float4*)(zs + c * 92);
            float s1 = 0.f, s2 = 0.f;
            for (int t4 = q; t4 < 23; t4 += 4) {
                float4 v = zr[t4];
                s1 += v.x + v.y + v.z + v.w;
                s2 += v.x * v.x + v.y * v.y + v.z * v.z + v.w * v.w;
            }
            s1 += __shfl_xor_sync(0xffffffffu, s1, 1);
            s2 += __shfl_xor_sync(0xffffffffu, s2, 1);
            s1 += __shfl_xor_sync(0xffffffffu, s1, 2);
            s2 += __shfl_xor_sync(0xffffffffu, s2, 2);
            if (q == 0) { s1sh[c] = s1; redv[c] = s2 - s1 * s1 * flin; }
        }
        __syncthreads();
        if (tid < 32) {
            float v = redv[tid] + redv[tid + 32];
            v += __shfl_xor_sync(0xffffffffu, v, 16);
            v += __shfl_xor_sync(0xffffffffu, v, 8);
            v += __shfl_xor_sync(0xffffffffu, v, 4);
            v += __shfl_xor_sync(0xffffffffu, v, 2);
            v += __shfl_xor_sync(0xffffffffu, v, 1);
            if (tid == 0) s_rtr = 1.f / v;
        }
        __syncthreads();

        ull zz2[4][4];
        #pragma unroll
        for (int a = 0; a < 4; ++a)
            #pragma unroll
            for (int e = 0; e < 4; ++e) zz2[a][e] = 0ull;

        const ulonglong2* Z2 = (const ulonglong2*)zs;
        #pragma unroll 1
        for (int t4 = 0; t4 < 23; ++t4) {
            ulonglong2 uu[4], vv[4];
            #pragma unroll
            for (int a = 0; a < 4; ++a) uu[a] = Z2[(ti + 16 * a) * 23 + t4];
            #pragma unroll
            for (int e = 0; e < 4; ++e) vv[e] = Z2[(tj + 16 * e) * 23 + t4];
            #pragma unroll
            for (int a = 0; a < 4; ++a)
                #pragma unroll
                for (int e = 0; e < 4; ++e) {
                    fma2(zz2[a][e], uu[a].x, vv[e].x);
                    fma2(zz2[a][e], uu[a].y, vv[e].y);
                }
        }
        float rtr = s_rtr;
        #pragma unroll
        for (int a = 0; a < 4; ++a) {
            float s1i = s1sh[ti + 16 * a] * flin * rtr;
            #pragma unroll
            for (int e = 0; e < 4; ++e) {
                float lo, hi; upk2(zz2[a][e], lo, hi);
                acc[a][e] += rtr * (lo + hi) - s1i * s1sh[tj + 16 * e];
            }
        }
    }
    __syncthreads();
    {
        float* A = zs;
        #pragma unroll
        for (int a = 0; a < 4; ++a)
            #pragma unroll
            for (int e = 0; e < 4; ++e)
                A[(ti + 16 * a) * 68 + tj + 16 * e] = acc[a][e];
    }
    __syncthreads();
    {
        const ulonglong2* A2 = (const ulonglong2*)zs;
        ulonglong2* B2 = (ulonglong2*)Bsh;
        #pragma unroll
        for (int pass = 0; pass < 2; ++pass) {
            int u0 = tid + pass * 256;
            int o = u0 >> 4, c4 = u0 & 15;
            ull a2a = 0ull, a2b = 0ull;
            const float* wrow = Wsh + o * 64;
            #pragma unroll 4
            for (int k = 0; k < 64; ++k) {
                float w = wrow[k];
                ull w2 = pk2(w, w);
                ulonglong2 av = A2[k * 17 + c4];
                fma2(a2a, av.x, w2);
                fma2(a2b, av.y, w2);
            }
            ulonglong2 st; st.x = a2a; st.y = a2b;
            B2[o * 18 + c4] = st;
        }
    }
    __syncthreads();
    if (tid < 64) {
        int o0 = (tid >> 3) * 4, p0 = (tid & 7) * 4;
        ull y2[4][4], wa2[4][4];
        #pragma unroll
        for (int a = 0; a < 4; ++a)
            #pragma unroll
            for (int e = 0; e < 4; ++e) { y2[a][e] = 0ull; wa2[a][e] = 0ull; }

        const ulonglong2* B2 = (const ulonglong2*)Bsh;
        const ulonglong2* W2 = (const ulonglong2*)Wsh;
        #pragma unroll 2
        for (int c4 = 0; c4 < 16; ++c4) {
            ulonglong2 bo[4], wo[4], wp[4];
            #pragma unroll
            for (int a = 0; a < 4; ++a) {
                bo[a] = B2[(o0 + a) * 18 + c4];
                wo[a] = W2[(o0 + a) * 16 + c4];
            }
            #pragma unroll
            for (int e = 0; e < 4; ++e) wp[e] = W2[(p0 + e) * 16 + c4];
            #pragma unroll
            for (int a = 0; a < 4; ++a)
                #pragma unroll
                for (int e = 0; e < 4; ++e) {
                    fma2(y2[a][e], bo[a].x, wp[e].x);
                    fma2(y2[a][e], bo[a].y, wp[e].y);
                    fma2(wa2[a][e], wo[a].x, wp[e].x);
                    fma2(wa2[a][e], wo[a].y, wp[e].y);
                }
        }
        #pragma unroll
        for (int a = 0; a < 4; ++a) {
            float4 ov;
            float lo, hi, wl, wh;
            upk2(y2[a][0], lo, hi); upk2(wa2[a][0], wl, wh);
            ov.x = (lo + hi) * (1.f / 3.f) + 1e-5f * (wl + wh);
            upk2(y2[a][1], lo, hi); upk2(wa2[a][1], wl, wh);
            ov.y = (lo + hi) * (1.f / 3.f) + 1e-5f * (wl + wh);
            upk2(y2[a][2], lo, hi); upk2(wa2[a][2], wl, wh);
            ov.z = (lo + hi) * (1.f / 3.f) + 1e-5f * (wl + wh);
            upk2(y2[a][3], lo, hi); upk2(wa2[a][3], wl, wh);
            ov.w = (lo + hi) * (1.f / 3.f) + 1e-5f * (wl + wh);
            *(float4*)(g_y + (size_t)b * 1024 + (o0 + a) * 32 + p0) = ov;
        }
    }
}

// ============================================================
// K3: one warp per 32x32 SPD: Hestenes Jacobi (6 sweeps),
//     logm = U log(max(lam,1e-4)) U^T, scaled triu -> fe
// ============================================================
__global__ void __launch_bounds__(256)
k_eig(float* __restrict__ feout)
{
    __shared__ float sm[8 * 1088];

    int tid = threadIdx.x;
    int wid = tid >> 5, lane = tid & 31;
    int b = blockIdx.x * 8 + wid;
    if (b >= BB) return;

    const float* Y = g_y + (size_t)b * 1024;
    float a[32];
    #pragma unroll
    for (int i = 0; i < 32; ++i) a[i] = Y[i * 32 + lane];

    for (int sweep = 0; sweep < 6; ++sweep) {
        for (int r = 0; r < 31; ++r) {
            int partner;
            if (lane == 0) partner = (30 + r) % 31 + 1;
            else {
                int pos = ((lane - 1 - r) % 31 + 31) % 31 + 1;
                int pp = 31 - pos;
                partner = (pp == 0) ? 0 : ((pp - 1 + r) % 31) + 1;
            }
            float oth[32];
            #pragma unroll
            for (int i = 0; i < 32; ++i)
                oth[i] = __shfl_sync(0xffffffffu, a[i], partner);
            float own = 0.f, dot = 0.f;
            #pragma unroll
            for (int i = 0; i < 32; ++i) { own += a[i] * a[i]; dot += a[i] * oth[i]; }
            float othn = __shfl_sync(0xffffffffu, own, partner);
            bool isp = lane < partner;
            float app = isp ? own : othn;
            float aqq = isp ? othn : own;
            float c = 1.f, s = 0.f;
            if (dot * dot > 1e-24f * app * aqq) {
                float zeta = (aqq - app) / (2.f * dot);
                float t = ((zeta >= 0.f) ? 1.f : -1.f) /
                          (fabsf(zeta) + sqrtf(1.f + zeta * zeta));
                c = rsqrtf(1.f + t * t);
                s = c * t;
            }
            #pragma unroll
            for (int i = 0; i < 32; ++i)
                a[i] = isp ? (c * a[i] - s * oth[i]) : (s * oth[i] + c * a[i]);
        }
    }

    float own = 0.f;
    #pragma unroll
    for (int i = 0; i < 32; ++i) own += a[i] * a[i];
    float lam = sqrtf(own);
    float g = logf(fmaxf(lam, 1e-4f));
    float inv = 1.f / lam;

    float* Us = sm + wid * 1088;
    float* gs = Us + 1056;
    #pragma unroll
    for (int i = 0; i < 32; ++i) Us[lane * 33 + i] = a[i] * inv;
    gs[lane] = g;
    __syncwarp();

    float scal[32];
    #pragma unroll
    for (int j = 0; j < 32; ++j) scal[j] = gs[j] * Us[j * 33 + lane];
    float acc[32];
    #pragma unroll
    for (int i = 0; i < 32; ++i) acc[i] = 0.f;
    #pragma unroll
    for (int j = 0; j < 32; ++j) {
        float sj = scal[j];
        #pragma unroll
        for (int i = 0; i < 32; ++i) acc[i] += sj * Us[j * 33 + i];
    }

    const float SQ2 = 1.41421356237309515f;
    int bi = 32 * lane - (lane * (lane - 1)) / 2 - lane;
    float* fb = feout + (size_t)b * NFE + bi;
    #pragma unroll
    for (int j = 0; j < 32; ++j) {
        if (j >= lane) fb[j] = acc[j] * ((j == lane) ? 1.f : SQ2);
    }
}

// ============================================================
// K4: logits(256,4) = fe(256,4752) @ Wl(4,4752)^T + bl
// ============================================================
__global__ void __launch_bounds__(128)
k_linear(const float* __restrict__ fe, const float* __restrict__ Wl,
         const float* __restrict__ bl, float* __restrict__ out)
{
    __shared__ float red[128 * 4];
    int bs = blockIdx.x, tid = threadIdx.x;
    const float* fr = fe + (size_t)bs * 4752;
    float acc[4] = {0.f, 0.f, 0.f, 0.f};
    for (int i = tid; i < 4752; i += 128) {
        float v = fr[i];
        #pragma unroll
        for (int c = 0; c < 4; ++c) acc[c] += v * Wl[c * 4752 + i];
    }
    #pragma unroll
    for (int c = 0; c < 4; ++c) red[tid * 4 + c] = acc[c];
    __syncthreads();
    for (int s = 64; s > 0; s >>= 1) {
        if (tid < s) {
            #pragma unroll
            for (int c = 0; c < 4; ++c) red[tid * 4 + c] += red[(tid + s) * 4 + c];
        }
        __syncthreads();
    }
    if (tid < 4) out[bs * 4 + tid] = red[tid] + bl[tid];
}

extern "C" void kernel_launch(void* const* d_in, const int* in_sizes, int n_in,
                              void* d_out, int out_size) {
    const float* x   = (const float*)d_in[0];
    const float* cw  = (const float*)d_in[1];
    const float* cb  = (const float*)d_in[2];
    const float* bg  = (const float*)d_in[3];
    const float* bb  = (const float*)d_in[4];
    const float* bm  = (const float*)d_in[5];
    const float* bv  = (const float*)d_in[6];
    const float* W   = (const float*)d_in[7];
    const float* Wl  = (const float*)d_in[8];
    const float* bl  = (const float*)d_in[9];
    float* fe     = (float*)d_out;
    float* logits = fe + (size_t)BB * NFE;

    static int smem_set = 0;
    if (!smem_set) {
        cudaFuncSetAttribute(k_conv, cudaFuncAttributeMaxDynamicSharedMemorySize,
                             CONV_SMEM);
        smem_set = 1;
    }

    k_wpack<<<(ST * 286 + 255) / 256, 256>>>(cw);
    k_prep<<<BB, 128>>>(x);
    k_conv<<<dim3(2, BB), 256, CONV_SMEM>>>(cb, bg, bb, bm, bv);
    k_covmap<<<BB, 256>>>(W);
    k_eig<<<BB / 8, 256>>>(fe);
    k_linear<<<256, 128>>>(fe, Wl, bl, logits);
}

// round 13
// speedup vs baseline: 1.1794x; 1.0278x over previous
#include <cuda_runtime.h>
#include <cuda_bf16.h>
#include <math.h>

#define BB    2304
#define CH    22
#define TP    250
#define ST    64
#define KW    13
#define RR    32
#define NFE   528

typedef unsigned long long ull;

__device__ float g_z[(size_t)BB * ST * TP];
__device__ float g_y[(size_t)BB * RR * RR];
__device__ float g_xp[(size_t)BB * CH * 272];   // pooled + padded input
__device__ ull   g_w2[ST * 286];                // (w,w) packed weights
__device__ float g_A3[(size_t)BB * 3 * 4096];   // per (b,blk) scaled cov slabs

__device__ __forceinline__ ull pk2(float a, float b) {
    ull r;
    asm("mov.b64 %0, {%1, %2};" : "=l"(r)
        : "r"(__float_as_uint(a)), "r"(__float_as_uint(b)));
    return r;
}
__device__ __forceinline__ void upk2(ull v, float &a, float &b) {
    unsigned int lo, hi;
    asm("mov.b64 {%0, %1}, %2;" : "=r"(lo), "=r"(hi) : "l"(v));
    a = __uint_as_float(lo); b = __uint_as_float(hi);
}
__device__ __forceinline__ void fma2(ull &d, ull a, ull b) {
    asm("fma.rn.f32x2 %0, %1, %2, %0;" : "+l"(d) : "l"(a), "l"(b));
}

// ============================================================
// K0a: pool(4) + zero-pad once per b -> g_xp[b][c][272]
// ============================================================
__global__ void __launch_bounds__(128)
k_prep(const float* __restrict__ x)
{
    int b = blockIdx.x, tid = threadIdx.x;
    const float4* xb = (const float4*)(x + (size_t)b * CH * 1000);
    float* dst = g_xp + (size_t)b * CH * 272;
    for (int i = tid; i < CH * 272; i += 128) {
        int c = i / 272, tt = i - c * 272;
        float v = 0.f;
        if (tt >= 6 && tt < 256) {
            float4 p = xb[c * TP + (tt - 6)];
            v = 0.25f * (p.x + p.y + p.z + p.w);
        }
        dst[i] = v;
    }
}

// K0b: pack conv weights as (w,w) ull pairs
__global__ void __launch_bounds__(256)
k_wpack(const float* __restrict__ cw)
{
    int i = blockIdx.x * 256 + threadIdx.x;
    if (i < ST * 286) {
        float w = cw[i];
        g_w2[i] = pk2(w, w);
    }
}

// ============================================================
// K1: conv(22x13) + BN -> g_z[b][o][t]   (unchanged from R12 winner)
// ============================================================
#define W2S_PITCH 287
#define CONV_SMEM (CH * 272 * 4 + 32 * W2S_PITCH * 8)

__global__ void __launch_bounds__(256, 2)
k_conv(const float* __restrict__ cb, const float* __restrict__ bg,
       const float* __restrict__ bbv, const float* __restrict__ bm,
       const float* __restrict__ bv)
{
    extern __shared__ float dsm[];
    float* xp  = dsm;
    ull*   w2s = (ull*)(dsm + CH * 272);
    __shared__ float sc[32], sh[32];

    int og = blockIdx.x, b = blockIdx.y, tid = threadIdx.x;

    {
        const float4* src = (const float4*)(g_xp + (size_t)b * CH * 272);
        float4* d4 = (float4*)xp;
        for (int i = tid; i < CH * 272 / 4; i += 256) d4[i] = src[i];
        const ull* wsrc = g_w2 + og * 32 * 286;
        for (int i = tid; i < 32 * 286; i += 256) {
            int ol = i / 286, k = i - ol * 286;
            w2s[ol * W2S_PITCH + k] = wsrc[i];
        }
        if (tid < 32) {
            int o = og * 32 + tid;
            float inv = bg[o] * rsqrtf(bv[o] + 1e-5f);
            sc[tid] = inv;
            sh[tid] = cb[o] * inv + bbv[o] - bm[o] * inv;
        }
    }
    __syncthreads();

    int chunk = tid & 15;
    int ol0   = tid >> 4;
    int t0 = chunk * 16;

    ull A[2][8], Bv[2][9];
    #pragma unroll
    for (int oh = 0; oh < 2; ++oh) {
        #pragma unroll
        for (int u = 0; u < 8; ++u) A[oh][u] = 0ull;
        #pragma unroll
        for (int u = 0; u < 9; ++u) Bv[oh][u] = 0ull;
    }

    #pragma unroll 1
    for (int c = 0; c < CH; ++c) {
        const ulonglong2* pw = (const ulonglong2*)(xp + c * 272 + t0);
        ull e[14];
        #pragma unroll
        for (int q = 0; q < 7; ++q) {
            ulonglong2 v = pw[q];
            e[2 * q] = v.x; e[2 * q + 1] = v.y;
        }

        #pragma unroll
        for (int oh = 0; oh < 2; ++oh) {
            const ull* wr = w2s + (ol0 + oh * 16) * W2S_PITCH + c * 13;
            #pragma unroll
            for (int m = 0; m < 7; ++m) {
                ull wv = wr[2 * m];
                #pragma unroll
                for (int u = 0; u < 8; ++u) fma2(A[oh][u], e[m + u], wv);
            }
            #pragma unroll
            for (int m = 0; m < 6; ++m) {
                ull wv = wr[2 * m + 1];
                #pragma unroll
                for (int u = 0; u < 9; ++u) fma2(Bv[oh][u], e[m + u], wv);
            }
        }
    }

    #pragma unroll
    for (int oh = 0; oh < 2; ++oh) {
        int ol = ol0 + oh * 16;
        int o = og * 32 + ol;
        float scl = sc[ol], shf = sh[ol];
        float2* zr = (float2*)(g_z + ((size_t)b * ST + o) * TP + t0);
        #pragma unroll
        for (int u = 0; u < 8; ++u) {
            int t = t0 + 2 * u;
            if (t < TP) {
                float alo, ahi, blo, bhi, nlo, nhi;
                upk2(A[oh][u], alo, ahi);
                upk2(Bv[oh][u], blo, bhi);
                upk2(Bv[oh][u + 1], nlo, nhi);
                float2 st;
                st.x = (alo + bhi) * scl + shf;
                st.y = (ahi + nlo) * scl + shf;
                zr[u] = st;
            }
        }
    }
}

// ============================================================
// K2a: per (blk, b): slab = rtr*(Z Z^T - s1 s1^T / l) -> g_A3
// grid (3, BB), 256 threads, 3 blocks/SM.
// ============================================================
__global__ void __launch_bounds__(256, 3)
k_cov_a()
{
    __shared__ __align__(16) float zs[64 * 92];
    __shared__ float s1sh[64];
    __shared__ float redv[64];
    __shared__ float s_rtr;

    int blk = blockIdx.x, b = blockIdx.y, tid = threadIdx.x;
    int ti = tid >> 4, tj = tid & 15;

    const int offs[3] = {0, 84, 167};
    const int lens[3] = {84, 83, 83};
    int off = offs[blk], l = lens[blk];
    float flin = 1.f / (float)l;

    for (int i = tid; i < 64 * 92; i += 256) {
        int c = i / 92, t = i - c * 92;
        zs[i] = (t < l) ? g_z[((size_t)b * 64 + c) * TP + off + t] : 0.f;
    }
    __syncthreads();

    // per-channel s1 / s2
    {
        int c = tid >> 2, q = tid & 3;
        const float4* zr = (const float4*)(zs + c * 92);
        float s1 = 0.f, s2 = 0.f;
        for (int t4 = q; t4 < 21; t4 += 4) {
            float4 v = zr[t4];
            s1 += v.x + v.y + v.z + v.w;
            s2 += v.x * v.x + v.y * v.y + v.z * v.z + v.w * v.w;
        }
        s1 += __shfl_xor_sync(0xffffffffu, s1, 1);
        s2 += __shfl_xor_sync(0xffffffffu, s2, 1);
        s1 += __shfl_xor_sync(0xffffffffu, s1, 2);
        s2 += __shfl_xor_sync(0xffffffffu, s2, 2);
        if (q == 0) { s1sh[c] = s1; redv[c] = s2 - s1 * s1 * flin; }
    }
    __syncthreads();
    if (tid < 32) {
        float v = redv[tid] + redv[tid + 32];
        v += __shfl_xor_sync(0xffffffffu, v, 16);
        v += __shfl_xor_sync(0xffffffffu, v, 8);
        v += __shfl_xor_sync(0xffffffffu, v, 4);
        v += __shfl_xor_sync(0xffffffffu, v, 2);
        v += __shfl_xor_sync(0xffffffffu, v, 1);
        if (tid == 0) s_rtr = 1.f / v;
    }
    __syncthreads();

    // ZZ^T 4x4 tile (interleaved rows, stride 16)
    ull zz2[4][4];
    #pragma unroll
    for (int a = 0; a < 4; ++a)
        #pragma unroll
        for (int e = 0; e < 4; ++e) zz2[a][e] = 0ull;

    const ulonglong2* Z2 = (const ulonglong2*)zs;
    #pragma unroll 1
    for (int t4 = 0; t4 < 21; ++t4) {
        ulonglong2 uu[4], vv[4];
        #pragma unroll
        for (int a = 0; a < 4; ++a) uu[a] = Z2[(ti + 16 * a) * 23 + t4];
        #pragma unroll
        for (int e = 0; e < 4; ++e) vv[e] = Z2[(tj + 16 * e) * 23 + t4];
        #pragma unroll
        for (int a = 0; a < 4; ++a)
            #pragma unroll
            for (int e = 0; e < 4; ++e) {
                fma2(zz2[a][e], uu[a].x, vv[e].x);
                fma2(zz2[a][e], uu[a].y, vv[e].y);
            }
    }
    float rtr = s_rtr;
    float* slab = g_A3 + ((size_t)b * 3 + blk) * 4096;
    #pragma unroll
    for (int a = 0; a < 4; ++a) {
        int i = ti + 16 * a;
        float s1i = s1sh[i] * flin * rtr;
        #pragma unroll
        for (int e = 0; e < 4; ++e) {
            int j = tj + 16 * e;
            float lo, hi; upk2(zz2[a][e], lo, hi);
            slab[i * 64 + j] = rtr * (lo + hi) - s1i * s1sh[j];
        }
    }
}

// ============================================================
// K2b: per b: A = sum slabs; y = (1/3) W A W^T + 1e-5 W W^T
// ============================================================
__global__ void __launch_bounds__(256)
k_cov_b(const float* __restrict__ W)
{
    __shared__ __align__(16) float A[64 * 68];
    __shared__ __align__(16) float Wsh[32 * 64];
    __shared__ __align__(16) float Bsh[32 * 72];

    int b = blockIdx.x, tid = threadIdx.x;

    for (int i = tid; i < 2048; i += 256) Wsh[i] = W[i];
    {
        const float4* s0 = (const float4*)(g_A3 + (size_t)b * 3 * 4096);
        const float4* s1 = s0 + 1024;
        const float4* s2 = s0 + 2048;
        for (int i = tid; i < 1024; i += 256) {
            float4 a0 = s0[i], a1 = s1[i], a2 = s2[i];
            float4 r;
            r.x = a0.x + a1.x + a2.x;
            r.y = a0.y + a1.y + a2.y;
            r.z = a0.z + a1.z + a2.z;
            r.w = a0.w + a1.w + a2.w;
            int row = i >> 4, c4 = i & 15;
            *(float4*)(A + row * 68 + c4 * 4) = r;
        }
    }
    __syncthreads();

    // B = W * A
    {
        const ulonglong2* A2 = (const ulonglong2*)A;
        ulonglong2* B2 = (ulonglong2*)Bsh;
        #pragma unroll
        for (int pass = 0; pass < 2; ++pass) {
            int u0 = tid + pass * 256;
            int o = u0 >> 4, c4 = u0 & 15;
            ull a2a = 0ull, a2b = 0ull;
            const float* wrow = Wsh + o * 64;
            #pragma unroll 4
            for (int k = 0; k < 64; ++k) {
                float w = wrow[k];
                ull w2 = pk2(w, w);
                ulonglong2 av = A2[k * 17 + c4];
                fma2(a2a, av.x, w2);
                fma2(a2b, av.y, w2);
            }
            ulonglong2 st; st.x = a2a; st.y = a2b;
            B2[o * 18 + c4] = st;
        }
    }
    __syncthreads();
    if (tid < 64) {
        int o0 = (tid >> 3) * 4, p0 = (tid & 7) * 4;
        ull y2[4][4], wa2[4][4];
        #pragma unroll
        for (int a = 0; a < 4; ++a)
            #pragma unroll
            for (int e = 0; e < 4; ++e) { y2[a][e] = 0ull; wa2[a][e] = 0ull; }

        const ulonglong2* B2 = (const ulonglong2*)Bsh;
        const ulonglong2* W2 = (const ulonglong2*)Wsh;
        #pragma unroll 2
        for (int c4 = 0; c4 < 16; ++c4) {
            ulonglong2 bo[4], wo[4], wp[4];
            #pragma unroll
            for (int a = 0; a < 4; ++a) {
                bo[a] = B2[(o0 + a) * 18 + c4];
                wo[a] = W2[(o0 + a) * 16 + c4];
            }
            #pragma unroll
            for (int e = 0; e < 4; ++e) wp[e] = W2[(p0 + e) * 16 + c4];
            #pragma unroll
            for (int a = 0; a < 4; ++a)
                #pragma unroll
                for (int e = 0; e < 4; ++e) {
                    fma2(y2[a][e], bo[a].x, wp[e].x);
                    fma2(y2[a][e], bo[a].y, wp[e].y);
                    fma2(wa2[a][e], wo[a].x, wp[e].x);
                    fma2(wa2[a][e], wo[a].y, wp[e].y);
                }
        }
        #pragma unroll
        for (int a = 0; a < 4; ++a) {
            float4 ov;
            float lo, hi, wl, wh;
            upk2(y2[a][0], lo, hi); upk2(wa2[a][0], wl, wh);
            ov.x = (lo + hi) * (1.f / 3.f) + 1e-5f * (wl + wh);
            upk2(y2[a][1], lo, hi); upk2(wa2[a][1], wl, wh);
            ov.y = (lo + hi) * (1.f / 3.f) + 1e-5f * (wl + wh);
            upk2(y2[a][2], lo, hi); upk2(wa2[a][2], wl, wh);
            ov.z = (lo + hi) * (1.f / 3.f) + 1e-5f * (wl + wh);
            upk2(y2[a][3], lo, hi); upk2(wa2[a][3], wl, wh);
            ov.w = (lo + hi) * (1.f / 3.f) + 1e-5f * (wl + wh);
            *(float4*)(g_y + (size_t)b * 1024 + (o0 + a) * 32 + p0) = ov;
        }
    }
}

// ============================================================
// K3: one warp per 32x32 SPD: Hestenes Jacobi (6 sweeps),
//     logm = U log(max(lam,1e-4)) U^T, scaled triu -> fe
// ============================================================
__global__ void __launch_bounds__(256)
k_eig(float* __restrict__ feout)
{
    __shared__ float sm[8 * 1088];

    int tid = threadIdx.x;
    int wid = tid >> 5, lane = tid & 31;
    int b = blockIdx.x * 8 + wid;
    if (b >= BB) return;

    const float* Y = g_y + (size_t)b * 1024;
    float a[32];
    #pragma unroll
    for (int i = 0; i < 32; ++i) a[i] = Y[i * 32 + lane];

    for (int sweep = 0; sweep < 6; ++sweep) {
        for (int r = 0; r < 31; ++r) {
            int partner;
            if (lane == 0) partner = (30 + r) % 31 + 1;
            else {
                int pos = ((lane - 1 - r) % 31 + 31) % 31 + 1;
                int pp = 31 - pos;
                partner = (pp == 0) ? 0 : ((pp - 1 + r) % 31) + 1;
            }
            float oth[32];
            #pragma unroll
            for (int i = 0; i < 32; ++i)
                oth[i] = __shfl_sync(0xffffffffu, a[i], partner);
            float own = 0.f, dot = 0.f;
            #pragma unroll
            for (int i = 0; i < 32; ++i) { own += a[i] * a[i]; dot += a[i] * oth[i]; }
            float othn = __shfl_sync(0xffffffffu, own, partner);
            bool isp = lane < partner;
            float app = isp ? own : othn;
            float aqq = isp ? othn : own;
            float c = 1.f, s = 0.f;
            if (dot * dot > 1e-24f * app * aqq) {
                float zeta = (aqq - app) / (2.f * dot);
                float t = ((zeta >= 0.f) ? 1.f : -1.f) /
                          (fabsf(zeta) + sqrtf(1.f + zeta * zeta));
                c = rsqrtf(1.f + t * t);
                s = c * t;
            }
            #pragma unroll
            for (int i = 0; i < 32; ++i)
                a[i] = isp ? (c * a[i] - s * oth[i]) : (s * oth[i] + c * a[i]);
        }
    }

    float own = 0.f;
    #pragma unroll
    for (int i = 0; i < 32; ++i) own += a[i] * a[i];
    float lam = sqrtf(own);
    float g = logf(fmaxf(lam, 1e-4f));
    float inv = 1.f / lam;

    float* Us = sm + wid * 1088;
    float* gs = Us + 1056;
    #pragma unroll
    for (int i = 0; i < 32; ++i) Us[lane * 33 + i] = a[i] * inv;
    gs[lane] = g;
    __syncwarp();

    float scal[32];
    #pragma unroll
    for (int j = 0; j < 32; ++j) scal[j] = gs[j] * Us[j * 33 + lane];
    float acc[32];
    #pragma unroll
    for (int i = 0; i < 32; ++i) acc[i] = 0.f;
    #pragma unroll
    for (int j = 0; j < 32; ++j) {
        float sj = scal[j];
        #pragma unroll
        for (int i = 0; i < 32; ++i) acc[i] += sj * Us[j * 33 + i];
    }

    const float SQ2 = 1.41421356237309515f;
    int bi = 32 * lane - (lane * (lane - 1)) / 2 - lane;
    float* fb = feout + (size_t)b * NFE + bi;
    #pragma unroll
    for (int j = 0; j < 32; ++j) {
        if (j >= lane) fb[j] = acc[j] * ((j == lane) ? 1.f : SQ2);
    }
}

// ============================================================
// K4: logits(256,4) = fe(256,4752) @ Wl(4,4752)^T + bl
// ============================================================
__global__ void __launch_bounds__(128)
k_linear(const float* __restrict__ fe, const float* __restrict__ Wl,
         const float* __restrict__ bl, float* __restrict__ out)
{
    __shared__ float red[128 * 4];
    int bs = blockIdx.x, tid = threadIdx.x;
    const float* fr = fe + (size_t)bs * 4752;
    float acc[4] = {0.f, 0.f, 0.f, 0.f};
    for (int i = tid; i < 4752; i += 128) {
        float v = fr[i];
        #pragma unroll
        for (int c = 0; c < 4; ++c) acc[c] += v * Wl[c * 4752 + i];
    }
    #pragma unroll
    for (int c = 0; c < 4; ++c) red[tid * 4 + c] = acc[c];
    __syncthreads();
    for (int s = 64; s > 0; s >>= 1) {
        if (tid < s) {
            #pragma unroll
            for (int c = 0; c < 4; ++c) red[tid * 4 + c] += red[(tid + s) * 4 + c];
        }
        __syncthreads();
    }
    if (tid < 4) out[bs * 4 + tid] = red[tid] + bl[tid];
}

extern "C" void kernel_launch(void* const* d_in, const int* in_sizes, int n_in,
                              void* d_out, int out_size) {
    const float* x   = (const float*)d_in[0];
    const float* cw  = (const float*)d_in[1];
    const float* cb  = (const float*)d_in[2];
    const float* bg  = (const float*)d_in[3];
    const float* bb  = (const float*)d_in[4];
    const float* bm  = (const float*)d_in[5];
    const float* bv  = (const float*)d_in[6];
    const float* W   = (const float*)d_in[7];
    const float* Wl  = (const float*)d_in[8];
    const float* bl  = (const float*)d_in[9];
    float* fe     = (float*)d_out;
    float* logits = fe + (size_t)BB * NFE;

    static int smem_set = 0;
    if (!smem_set) {
        cudaFuncSetAttribute(k_conv, cudaFuncAttributeMaxDynamicSharedMemorySize,
                             CONV_SMEM);
        smem_set = 1;
    }

    k_wpack<<<(ST * 286 + 255) / 256, 256>>>(cw);
    k_prep<<<BB, 128>>>(x);
    k_conv<<<dim3(2, BB), 256, CONV_SMEM>>>(cb, bg, bb, bm, bv);
    k_cov_a<<<dim3(3, BB), 256>>>();
    k_cov_b<<<BB, 256>>>(W);
    k_eig<<<BB / 8, 256>>>(fe);
    k_linear<<<256, 128>>>(fe, Wl, bl, logits);
}